// round 1
// baseline (speedup 1.0000x reference)
#include <cuda_runtime.h>
#include <cstdint>

// Problem constants
#define BB   2
#define SS   2048
#define EE   1024
#define HH   16
#define DD   64
#define M1   (BB*SS)        // 4096
#define N1   (3*EE)         // 3072
#define KDIM 1024
#define SCALE 0.125f        // 1/sqrt(64)

// Scratch (allocation-free rule: __device__ globals)
__device__ float g_q[(size_t)BB*HH*SS*DD];     // [b][h][s][d]
__device__ float g_k[(size_t)BB*HH*SS*DD];
__device__ float g_v[(size_t)BB*HH*SS*DD];
__device__ float g_att[(size_t)BB*SS*EE];      // [b][s][h][d] == [b][s][e]

// ---------------------------------------------------------------------------
// GEMM 1: QKV projection.  C[m,n] = sum_k x[m,k] * qkv_w[n,k]
// M=4096, N=3072, K=1024.  128x128x8 tile, 256 threads, 8x8 per thread.
// Epilogue scatters into g_q/g_k/g_v in [b][h][s][d] layout.
// ---------------------------------------------------------------------------
__global__ __launch_bounds__(256) void qkv_gemm(const float* __restrict__ A,
                                                const float* __restrict__ W)
{
    __shared__ float As[8][128];   // As[k][m]
    __shared__ float Bs[8][128];   // Bs[k][n]

    const int bm  = blockIdx.y * 128;
    const int bn  = blockIdx.x * 128;
    const int tid = threadIdx.x;
    const int tx  = tid & 15;
    const int ty  = tid >> 4;
    const int lrow = tid >> 1;        // 0..127
    const int lk   = (tid & 1) * 4;   // 0 or 4

    float acc[8][8];
#pragma unroll
    for (int i = 0; i < 8; i++)
#pragma unroll
        for (int j = 0; j < 8; j++) acc[i][j] = 0.f;

    const float* Aptr = A + (size_t)(bm + lrow) * KDIM + lk;
    const float* Wptr = W + (size_t)(bn + lrow) * KDIM + lk;

    for (int k0 = 0; k0 < KDIM; k0 += 8) {
        float4 a = *(const float4*)(Aptr + k0);
        float4 b = *(const float4*)(Wptr + k0);
        As[lk+0][lrow] = a.x; As[lk+1][lrow] = a.y; As[lk+2][lrow] = a.z; As[lk+3][lrow] = a.w;
        Bs[lk+0][lrow] = b.x; Bs[lk+1][lrow] = b.y; Bs[lk+2][lrow] = b.z; Bs[lk+3][lrow] = b.w;
        __syncthreads();
#pragma unroll
        for (int kk = 0; kk < 8; kk++) {
            float4 a0 = *(const float4*)&As[kk][ty*4];
            float4 a1 = *(const float4*)&As[kk][ty*4 + 64];
            float4 b0 = *(const float4*)&Bs[kk][tx*4];
            float4 b1 = *(const float4*)&Bs[kk][tx*4 + 64];
            float ar[8] = {a0.x,a0.y,a0.z,a0.w,a1.x,a1.y,a1.z,a1.w};
            float br[8] = {b0.x,b0.y,b0.z,b0.w,b1.x,b1.y,b1.z,b1.w};
#pragma unroll
            for (int i = 0; i < 8; i++)
#pragma unroll
                for (int j = 0; j < 8; j++)
                    acc[i][j] = fmaf(ar[i], br[j], acc[i][j]);
        }
        __syncthreads();
    }

    // Epilogue: n = c*1024 + h*64 + d ; m = b*2048 + s
#pragma unroll
    for (int i = 0; i < 8; i++) {
        int m = bm + ((i < 4) ? (ty*4 + i) : (64 + ty*4 + (i - 4)));
        int bbi = m >> 11;
        int s   = m & 2047;
#pragma unroll
        for (int jj = 0; jj < 2; jj++) {
            int n = bn + jj*64 + tx*4;
            int c = n >> 10;
            int h = (n >> 6) & 15;
            int d = n & 63;
            float* dst = (c == 0) ? g_q : ((c == 1) ? g_k : g_v);
            float4 val = make_float4(acc[i][jj*4+0], acc[i][jj*4+1],
                                     acc[i][jj*4+2], acc[i][jj*4+3]);
            *(float4*)&dst[(((size_t)bbi*HH + h)*SS + s)*DD + d] = val;
        }
    }
}

// ---------------------------------------------------------------------------
// Fused flash-style attention. One CTA = one (b,h) and 64 query rows.
// 256 threads, 4x4 per thread on 64x64 tiles. Online softmax in registers.
// Writes g_att in [b][s][h][d] layout.
// ---------------------------------------------------------------------------
__global__ __launch_bounds__(256) void attn_kernel(const int* __restrict__ mask)
{
    __shared__ float Qs[64][64];   // Qs[d][r]  (transposed)
    __shared__ float KVs[64][64];  // K phase: Ks[d][t] (transposed); V phase: Vs[t][d]
    __shared__ float Ps[64][64];   // Ps[t][r]  (transposed probabilities)

    const int bh  = blockIdx.y;      // 0..31
    const int bbi = bh >> 4;
    const int hh  = bh & 15;
    const int q0  = blockIdx.x * 64;

    const float* Qg = g_q + (size_t)bh*SS*DD + (size_t)q0*DD;
    const float* Kg = g_k + (size_t)bh*SS*DD;
    const float* Vg = g_v + (size_t)bh*SS*DD;

    const int tid = threadIdx.x;
    const int tx  = tid & 15;
    const int ty  = tid >> 4;

    // Load Q tile transposed
#pragma unroll
    for (int it = 0; it < 4; it++) {
        int idx = tid + it*256;
        int r = idx >> 4, dg = (idx & 15) * 4;
        float4 val = *(const float4*)(Qg + r*DD + dg);
        Qs[dg+0][r] = val.x; Qs[dg+1][r] = val.y;
        Qs[dg+2][r] = val.z; Qs[dg+3][r] = val.w;
    }

    float m_i[4], l_i[4], o[4][4];
#pragma unroll
    for (int i = 0; i < 4; i++) {
        m_i[i] = -1e30f; l_i[i] = 0.f;
#pragma unroll
        for (int j = 0; j < 4; j++) o[i][j] = 0.f;
    }

    for (int kt = 0; kt < SS/64; kt++) {
        // Load K tile transposed into KVs
#pragma unroll
        for (int it = 0; it < 4; it++) {
            int idx = tid + it*256;
            int r = idx >> 4, dg = (idx & 15) * 4;
            float4 val = *(const float4*)(Kg + (size_t)(kt*64 + r)*DD + dg);
            KVs[dg+0][r] = val.x; KVs[dg+1][r] = val.y;
            KVs[dg+2][r] = val.z; KVs[dg+3][r] = val.w;
        }
        // Per-thread mask for its 4 key columns
        int4 mv = *(const int4*)&mask[bbi*SS + kt*64 + tx*4];
        __syncthreads();

        // S = Q @ K^T
        float sacc[4][4];
#pragma unroll
        for (int i = 0; i < 4; i++)
#pragma unroll
            for (int j = 0; j < 4; j++) sacc[i][j] = 0.f;
#pragma unroll
        for (int kk = 0; kk < 64; kk++) {
            float4 a = *(const float4*)&Qs[kk][ty*4];
            float4 b = *(const float4*)&KVs[kk][tx*4];
            float ar[4] = {a.x,a.y,a.z,a.w};
            float br[4] = {b.x,b.y,b.z,b.w};
#pragma unroll
            for (int i = 0; i < 4; i++)
#pragma unroll
                for (int j = 0; j < 4; j++)
                    sacc[i][j] = fmaf(ar[i], br[j], sacc[i][j]);
        }
        __syncthreads();  // everyone done reading K; safe to overwrite with V

        // Load V tile (natural layout) — overlaps with softmax below
#pragma unroll
        for (int it = 0; it < 4; it++) {
            int idx = tid + it*256;
            int r = idx >> 4, dg = (idx & 15) * 4;
            float4 val = *(const float4*)(Vg + (size_t)(kt*64 + r)*DD + dg);
            *(float4*)&KVs[r][dg] = val;
        }

        // Online softmax (row state replicated across the 16-lane tx group)
        int mr[4] = {mv.x, mv.y, mv.z, mv.w};
#pragma unroll
        for (int i = 0; i < 4; i++) {
            float mrow = -1e30f;
#pragma unroll
            for (int j = 0; j < 4; j++) {
                float sv = (mr[j] != 0) ? sacc[i][j] * SCALE : -1e30f;
                sacc[i][j] = sv;
                mrow = fmaxf(mrow, sv);
            }
#pragma unroll
            for (int off = 8; off; off >>= 1)
                mrow = fmaxf(mrow, __shfl_xor_sync(0xffffffffu, mrow, off, 16));
            float mnew  = fmaxf(m_i[i], mrow);
            float alpha = __expf(m_i[i] - mnew);
            float lsum  = 0.f;
#pragma unroll
            for (int j = 0; j < 4; j++) {
                float p = __expf(sacc[i][j] - mnew);
                sacc[i][j] = p;
                lsum += p;
            }
#pragma unroll
            for (int off = 8; off; off >>= 1)
                lsum += __shfl_xor_sync(0xffffffffu, lsum, off, 16);
            l_i[i] = l_i[i] * alpha + lsum;
            m_i[i] = mnew;
#pragma unroll
            for (int j = 0; j < 4; j++) o[i][j] *= alpha;
            // Store P transposed
#pragma unroll
            for (int j = 0; j < 4; j++) Ps[tx*4+j][ty*4+i] = sacc[i][j];
        }
        __syncthreads();  // V loaded + P written

        // O += P @ V
#pragma unroll
        for (int kk = 0; kk < 64; kk++) {
            float4 p  = *(const float4*)&Ps[kk][ty*4];
            float4 vv = *(const float4*)&KVs[kk][tx*4];
            float pr[4] = {p.x,p.y,p.z,p.w};
            float vr[4] = {vv.x,vv.y,vv.z,vv.w};
#pragma unroll
            for (int i = 0; i < 4; i++)
#pragma unroll
                for (int j = 0; j < 4; j++)
                    o[i][j] = fmaf(pr[i], vr[j], o[i][j]);
        }
        __syncthreads();  // before next K tile overwrites KVs/Ps
    }

    // Epilogue: normalize and write [b][s][h][d]
#pragma unroll
    for (int i = 0; i < 4; i++) {
        float inv = 1.f / l_i[i];
        int srow = q0 + ty*4 + i;
        float4 val = make_float4(o[i][0]*inv, o[i][1]*inv, o[i][2]*inv, o[i][3]*inv);
        *(float4*)&g_att[(((size_t)bbi*SS + srow)*HH + hh)*DD + tx*4] = val;
    }
}

// ---------------------------------------------------------------------------
// GEMM 3: output projection. out[m,n] = sum_k att[m,k]*out_w[n,k] + out_b[n]
// M=4096, N=1024, K=1024.
// ---------------------------------------------------------------------------
__global__ __launch_bounds__(256) void proj_gemm(const float* __restrict__ W,
                                                 const float* __restrict__ bias,
                                                 float* __restrict__ out)
{
    __shared__ float As[8][128];
    __shared__ float Bs[8][128];

    const int bm  = blockIdx.y * 128;
    const int bn  = blockIdx.x * 128;
    const int tid = threadIdx.x;
    const int tx  = tid & 15;
    const int ty  = tid >> 4;
    const int lrow = tid >> 1;
    const int lk   = (tid & 1) * 4;

    float acc[8][8];
#pragma unroll
    for (int i = 0; i < 8; i++)
#pragma unroll
        for (int j = 0; j < 8; j++) acc[i][j] = 0.f;

    const float* Aptr = g_att + (size_t)(bm + lrow) * KDIM + lk;
    const float* Wptr = W     + (size_t)(bn + lrow) * KDIM + lk;

    for (int k0 = 0; k0 < KDIM; k0 += 8) {
        float4 a = *(const float4*)(Aptr + k0);
        float4 b = *(const float4*)(Wptr + k0);
        As[lk+0][lrow] = a.x; As[lk+1][lrow] = a.y; As[lk+2][lrow] = a.z; As[lk+3][lrow] = a.w;
        Bs[lk+0][lrow] = b.x; Bs[lk+1][lrow] = b.y; Bs[lk+2][lrow] = b.z; Bs[lk+3][lrow] = b.w;
        __syncthreads();
#pragma unroll
        for (int kk = 0; kk < 8; kk++) {
            float4 a0 = *(const float4*)&As[kk][ty*4];
            float4 a1 = *(const float4*)&As[kk][ty*4 + 64];
            float4 b0 = *(const float4*)&Bs[kk][tx*4];
            float4 b1 = *(const float4*)&Bs[kk][tx*4 + 64];
            float ar[8] = {a0.x,a0.y,a0.z,a0.w,a1.x,a1.y,a1.z,a1.w};
            float br[8] = {b0.x,b0.y,b0.z,b0.w,b1.x,b1.y,b1.z,b1.w};
#pragma unroll
            for (int i = 0; i < 8; i++)
#pragma unroll
                for (int j = 0; j < 8; j++)
                    acc[i][j] = fmaf(ar[i], br[j], acc[i][j]);
        }
        __syncthreads();
    }

#pragma unroll
    for (int i = 0; i < 8; i++) {
        int m = bm + ((i < 4) ? (ty*4 + i) : (64 + ty*4 + (i - 4)));
#pragma unroll
        for (int jj = 0; jj < 2; jj++) {
            int n = bn + jj*64 + tx*4;
            float4 bsv = *(const float4*)&bias[n];
            float4 val = make_float4(acc[i][jj*4+0] + bsv.x, acc[i][jj*4+1] + bsv.y,
                                     acc[i][jj*4+2] + bsv.z, acc[i][jj*4+3] + bsv.w);
            *(float4*)&out[(size_t)m*EE + n] = val;
        }
    }
}

// ---------------------------------------------------------------------------
extern "C" void kernel_launch(void* const* d_in, const int* in_sizes, int n_in,
                              void* d_out, int out_size)
{
    const float* x      = (const float*)d_in[0];
    const int*   mask   = (const int*)  d_in[1];
    const float* qkv_w  = (const float*)d_in[2];
    const float* out_w  = (const float*)d_in[3];
    const float* out_b  = (const float*)d_in[4];
    float*       out    = (float*)d_out;

    dim3 block(256);
    dim3 g1(N1/128, M1/128);       // 24 x 32
    qkv_gemm<<<g1, block>>>(x, qkv_w);

    dim3 g2(SS/64, BB*HH);         // 32 x 32
    attn_kernel<<<g2, block>>>(mask);

    dim3 g3(EE/128, M1/128);       // 8 x 32
    proj_gemm<<<g3, block>>>(out_w, out_b, out);
}

// round 3
// speedup vs baseline: 3.1376x; 3.1376x over previous
#include <cuda_runtime.h>
#include <cuda_bf16.h>
#include <cstdint>

#define BB   2
#define SS   2048
#define EE   1024
#define HH   16
#define DD   64
#define M1   4096
#define N1   3072
#define KDIM 1024
#define SCALE 0.125f

// ---------------------------------------------------------------------------
// helpers
// ---------------------------------------------------------------------------
__device__ __forceinline__ uint32_t smem_u32(const void* p) {
    uint32_t a;
    asm("{ .reg .u64 t; cvta.to.shared.u64 t, %1; cvt.u32.u64 %0, t; }" : "=r"(a) : "l"(p));
    return a;
}
#define SWZ(x) ((x) ^ (((x) >> 3) & 0x70))

#define CP16(dst, src) \
    asm volatile("cp.async.cg.shared.global [%0], [%1], 16;" :: "r"(dst), "l"(src))
#define CP_COMMIT() asm volatile("cp.async.commit_group;" ::: "memory")
#define CP_WAIT(n)  asm volatile("cp.async.wait_group %0;" :: "n"(n) : "memory")

#define LDSM4(r0,r1,r2,r3,a) \
    asm volatile("ldmatrix.sync.aligned.m8n8.x4.shared.b16 {%0,%1,%2,%3}, [%4];" \
                 : "=r"(r0),"=r"(r1),"=r"(r2),"=r"(r3) : "r"(a))
#define LDSM4T(r0,r1,r2,r3,a) \
    asm volatile("ldmatrix.sync.aligned.m8n8.x4.trans.shared.b16 {%0,%1,%2,%3}, [%4];" \
                 : "=r"(r0),"=r"(r1),"=r"(r2),"=r"(r3) : "r"(a))

__device__ __forceinline__ void mma16816(float* d, const uint32_t* a, const uint32_t* b) {
    asm volatile(
        "mma.sync.aligned.m16n8k16.row.col.f32.bf16.bf16.f32 "
        "{%0,%1,%2,%3}, {%4,%5,%6,%7}, {%8,%9}, {%0,%1,%2,%3};"
        : "+f"(d[0]), "+f"(d[1]), "+f"(d[2]), "+f"(d[3])
        : "r"(a[0]), "r"(a[1]), "r"(a[2]), "r"(a[3]), "r"(b[0]), "r"(b[1]));
}

__device__ __forceinline__ uint32_t packbf(__nv_bfloat16 a, __nv_bfloat16 b) {
    __nv_bfloat162 t; t.x = a; t.y = b;
    return *reinterpret_cast<uint32_t*>(&t);
}
__device__ __forceinline__ void splitpack2(float v0, float v1, uint32_t& hi, uint32_t& lo) {
    __nv_bfloat16 h0 = __float2bfloat16(v0), h1 = __float2bfloat16(v1);
    __nv_bfloat16 l0 = __float2bfloat16(v0 - __bfloat162float(h0));
    __nv_bfloat16 l1 = __float2bfloat16(v1 - __bfloat162float(h1));
    hi = packbf(h0, h1); lo = packbf(l0, l1);
}

// ---------------------------------------------------------------------------
// scratch (__device__ globals)
// ---------------------------------------------------------------------------
#define QKV_ELEMS ((size_t)BB*HH*SS*DD)
__device__ __nv_bfloat16 g_qhi[QKV_ELEMS], g_qlo[QKV_ELEMS];
__device__ __nv_bfloat16 g_khi[QKV_ELEMS], g_klo[QKV_ELEMS];
__device__ __nv_bfloat16 g_vhi[QKV_ELEMS], g_vlo[QKV_ELEMS];
__device__ __nv_bfloat16 g_xhi[(size_t)M1*KDIM],  g_xlo[(size_t)M1*KDIM];
__device__ __nv_bfloat16 g_wqhi[(size_t)N1*KDIM], g_wqlo[(size_t)N1*KDIM];
__device__ __nv_bfloat16 g_wohi[(size_t)EE*KDIM], g_wolo[(size_t)EE*KDIM];
__device__ __nv_bfloat16 g_atthi[(size_t)M1*EE],  g_attlo[(size_t)M1*EE];

// ---------------------------------------------------------------------------
// fp32 -> bf16 hi/lo split
// ---------------------------------------------------------------------------
__global__ __launch_bounds__(256) void split_bf16(const float* __restrict__ in,
                                                  __nv_bfloat16* __restrict__ hi,
                                                  __nv_bfloat16* __restrict__ lo,
                                                  int n4)
{
    int i = blockIdx.x * blockDim.x + threadIdx.x;
    if (i >= n4) return;
    float4 v = ((const float4*)in)[i];
    uint32_t h01, l01, h23, l23;
    splitpack2(v.x, v.y, h01, l01);
    splitpack2(v.z, v.w, h23, l23);
    ((uint2*)hi)[i] = make_uint2(h01, h23);
    ((uint2*)lo)[i] = make_uint2(l01, l23);
}

// ---------------------------------------------------------------------------
// HMMA GEMM: C[M,N] = (Ahi+Alo)[M,K] @ (Bhi+Blo)[N,K]^T  (3-term split)
// 128x128 tile, 8 warps (64x32 warp tiles), K chunks of 64, cp.async 2-stage.
// mode 0: scatter q/k/v as bf16 hi/lo (q scaled); mode 1: fp32 out + bias.
// ---------------------------------------------------------------------------
#define GSTG 65536
#define GSMEM (2*GSTG)

__global__ __launch_bounds__(256, 1) void mm_mma(
    const __nv_bfloat16* __restrict__ Ahi, const __nv_bfloat16* __restrict__ Alo,
    const __nv_bfloat16* __restrict__ Bhi, const __nv_bfloat16* __restrict__ Blo,
    float* __restrict__ Cout, const float* __restrict__ bias, int mode)
{
    extern __shared__ char smc[];
    const int tid = threadIdx.x, lane = tid & 31, w = tid >> 5;
    const int wr = w >> 2, wc = w & 3;
    const int bm = blockIdx.y * 128, bn = blockIdx.x * 128;
    const uint32_t smb = smem_u32(smc);

    auto load_stage = [&](int st, int ch) {
        const int koff = ch * 64;
#pragma unroll
        for (int t = 0; t < 4; t++) {
            const __nv_bfloat16* src = (t == 0) ? Ahi : (t == 1) ? Alo : (t == 2) ? Bhi : Blo;
            const int row0 = (t < 2) ? bm : bn;
#pragma unroll
            for (int i = 0; i < 4; i++) {
                int cid = tid + i * 256;
                int r = cid >> 3, c = cid & 7;
                uint32_t sa = smb + st * GSTG + t * 16384 + SWZ(r * 128 + c * 16);
                const char* ga = (const char*)(src + (size_t)(row0 + r) * KDIM + koff) + c * 16;
                CP16(sa, ga);
            }
        }
    };

    float acc[4][4][4];
#pragma unroll
    for (int i = 0; i < 4; i++)
#pragma unroll
        for (int j = 0; j < 4; j++)
#pragma unroll
            for (int q = 0; q < 4; q++) acc[i][j][q] = 0.f;

    load_stage(0, 0); CP_COMMIT();

    const int aro  = (lane & 7) + 8 * ((lane >> 3) & 1);
    const int csel = 16 * (lane >> 4);

    for (int ch = 0; ch < 16; ch++) {
        const int st = ch & 1;
        if (ch + 1 < 16) { load_stage(st ^ 1, ch + 1); CP_COMMIT(); CP_WAIT(1); }
        else             { CP_WAIT(0); }
        __syncthreads();

        const uint32_t sAh = smb + st * GSTG;
        const uint32_t sAl = sAh + 16384;
        const uint32_t sBh = sAh + 32768;
        const uint32_t sBl = sAh + 49152;

#pragma unroll
        for (int ks = 0; ks < 4; ks++) {
            const int colb = ks * 32 + csel;
            uint32_t ah[4][4], al[4][4];
#pragma unroll
            for (int i = 0; i < 4; i++) {
                uint32_t off = SWZ((wr * 64 + i * 16 + aro) * 128 + colb);
                LDSM4(ah[i][0], ah[i][1], ah[i][2], ah[i][3], sAh + off);
                LDSM4(al[i][0], al[i][1], al[i][2], al[i][3], sAl + off);
            }
            uint32_t bhf[4][2], blf[4][2];
#pragma unroll
            for (int g = 0; g < 2; g++) {
                uint32_t off = SWZ((wc * 32 + g * 16 + aro) * 128 + colb);
                uint32_t r0, r1, r2, r3;
                LDSM4(r0, r1, r2, r3, sBh + off);
                bhf[2*g][0] = r0; bhf[2*g][1] = r2; bhf[2*g+1][0] = r1; bhf[2*g+1][1] = r3;
                LDSM4(r0, r1, r2, r3, sBl + off);
                blf[2*g][0] = r0; blf[2*g][1] = r2; blf[2*g+1][0] = r1; blf[2*g+1][1] = r3;
            }
#pragma unroll
            for (int i = 0; i < 4; i++)
#pragma unroll
                for (int j = 0; j < 4; j++) {
                    mma16816(acc[i][j], ah[i], bhf[j]);
                    mma16816(acc[i][j], ah[i], blf[j]);
                    mma16816(acc[i][j], al[i], bhf[j]);
                }
        }
        __syncthreads();
    }

    // epilogue
#pragma unroll
    for (int i = 0; i < 4; i++) {
        int mrow = bm + wr * 64 + i * 16 + (lane >> 2);
#pragma unroll
        for (int j = 0; j < 4; j++) {
            int n = bn + wc * 32 + j * 8 + (lane & 3) * 2;
            if (mode == 0) {
                int c = n >> 10, h = (n >> 6) & 15, d = n & 63;
                float sc = (c == 0) ? SCALE : 1.0f;
                __nv_bfloat16* dh = (c == 0) ? g_qhi : (c == 1) ? g_khi : g_vhi;
                __nv_bfloat16* dl = (c == 0) ? g_qlo : (c == 1) ? g_klo : g_vlo;
#pragma unroll
                for (int rr = 0; rr < 2; rr++) {
                    int m = mrow + rr * 8;
                    int b = m >> 11, s = m & 2047;
                    float v0 = acc[i][j][2*rr + 0] * sc;
                    float v1 = acc[i][j][2*rr + 1] * sc;
                    uint32_t hi, lo;
                    splitpack2(v0, v1, hi, lo);
                    size_t idx = (((size_t)b * HH + h) * SS + s) * DD + d;
                    *(uint32_t*)&dh[idx] = hi;
                    *(uint32_t*)&dl[idx] = lo;
                }
            } else {
                float2 b2 = *(const float2*)&bias[n];
                float2 o0 = make_float2(acc[i][j][0] + b2.x, acc[i][j][1] + b2.y);
                float2 o1 = make_float2(acc[i][j][2] + b2.x, acc[i][j][3] + b2.y);
                *(float2*)&Cout[(size_t)mrow * EE + n] = o0;
                *(float2*)&Cout[(size_t)(mrow + 8) * EE + n] = o1;
            }
        }
    }
}

// ---------------------------------------------------------------------------
// FA2-style HMMA attention. CTA = (b,h) x 128 q-rows; 8 warps, 16 rows each.
// KV tiles of 64 keys, 2-stage cp.async pipeline. q pre-scaled by 1/sqrt(d).
// ---------------------------------------------------------------------------
#define AKV0 32768
#define ASTG 32768
#define ASMEM (AKV0 + 2*ASTG)   // 96 KB

__global__ __launch_bounds__(256, 1) void attn_mma(const int* __restrict__ mask)
{
    extern __shared__ char smc[];
    __shared__ float msk[2][64];
    const int tid = threadIdx.x, lane = tid & 31, w = tid >> 5;
    const int bh = blockIdx.y, bbi = bh >> 4, hh = bh & 15;
    const int q0 = blockIdx.x * 128;
    const uint32_t smb = smem_u32(smc);
    const uint32_t sQh = smb, sQl = smb + 16384;

    const size_t bhoff = (size_t)bh * SS * DD;
    const __nv_bfloat16* Khg = g_khi + bhoff;
    const __nv_bfloat16* Klg = g_klo + bhoff;
    const __nv_bfloat16* Vhg = g_vhi + bhoff;
    const __nv_bfloat16* Vlg = g_vlo + bhoff;
    const __nv_bfloat16* Qhg = g_qhi + bhoff + (size_t)q0 * DD;
    const __nv_bfloat16* Qlg = g_qlo + bhoff + (size_t)q0 * DD;

    // Q tile: 128 x 64 bf16, hi+lo
#pragma unroll
    for (int i = 0; i < 4; i++) {
        int cid = tid + i * 256;
        int r = cid >> 3, c = cid & 7;
        uint32_t so = SWZ(r * 128 + c * 16);
        CP16(sQh + so, (const char*)(Qhg + (size_t)r * DD) + c * 16);
        CP16(sQl + so, (const char*)(Qlg + (size_t)r * DD) + c * 16);
    }
    CP_COMMIT();

    auto load_kv = [&](int st, int kt) {
        uint32_t base = smb + AKV0 + st * ASTG;
        const int s0 = kt * 64;
#pragma unroll
        for (int i = 0; i < 2; i++) {
            int cid = tid + i * 256;
            int r = cid >> 3, c = cid & 7;
            uint32_t so = SWZ(r * 128 + c * 16);
            size_t go = (size_t)(s0 + r) * DD;
            CP16(base + so,         (const char*)(Khg + go) + c * 16);
            CP16(base + 8192 + so,  (const char*)(Klg + go) + c * 16);
            CP16(base + 16384 + so, (const char*)(Vhg + go) + c * 16);
            CP16(base + 24576 + so, (const char*)(Vlg + go) + c * 16);
        }
    };
    load_kv(0, 0); CP_COMMIT();
    if (tid < 64) msk[0][tid] = mask[bbi * SS + tid] ? 0.f : -1e30f;
    CP_WAIT(1);
    __syncthreads();

    const int aro  = (lane & 7) + 8 * ((lane >> 3) & 1);
    const int csel = 16 * (lane >> 4);

    // Q fragments (persist in registers)
    uint32_t qh[4][4], ql[4][4];
#pragma unroll
    for (int ks = 0; ks < 4; ks++) {
        uint32_t off = SWZ((w * 16 + aro) * 128 + ks * 32 + csel);
        LDSM4(qh[ks][0], qh[ks][1], qh[ks][2], qh[ks][3], sQh + off);
        LDSM4(ql[ks][0], ql[ks][1], ql[ks][2], ql[ks][3], sQl + off);
    }

    float o[8][4];
#pragma unroll
    for (int j = 0; j < 8; j++)
#pragma unroll
        for (int q = 0; q < 4; q++) o[j][q] = 0.f;
    float mi0 = -1e30f, mi1 = -1e30f, li0 = 0.f, li1 = 0.f;

    for (int kt = 0; kt < 32; kt++) {
        const int st = kt & 1;
        if (kt + 1 < 32) {
            load_kv(st ^ 1, kt + 1); CP_COMMIT();
            if (tid < 64) msk[st ^ 1][tid] = mask[bbi * SS + (kt + 1) * 64 + tid] ? 0.f : -1e30f;
            CP_WAIT(1);
        } else CP_WAIT(0);
        __syncthreads();

        const uint32_t sKh = smb + AKV0 + st * ASTG;
        const uint32_t sKl = sKh + 8192;
        const uint32_t sVh = sKh + 16384;
        const uint32_t sVl = sKh + 24576;

        // S = Q @ K^T (scaled via pre-scaled Q)
        float s[8][4];
#pragma unroll
        for (int j = 0; j < 8; j++)
#pragma unroll
            for (int q = 0; q < 4; q++) s[j][q] = 0.f;
#pragma unroll
        for (int ks = 0; ks < 4; ks++) {
            const int colb = ks * 32 + csel;
            uint32_t kb[8][2], kl[8][2];
#pragma unroll
            for (int g = 0; g < 4; g++) {
                uint32_t off = SWZ((g * 16 + aro) * 128 + colb);
                uint32_t r0, r1, r2, r3;
                LDSM4(r0, r1, r2, r3, sKh + off);
                kb[2*g][0] = r0; kb[2*g][1] = r2; kb[2*g+1][0] = r1; kb[2*g+1][1] = r3;
                LDSM4(r0, r1, r2, r3, sKl + off);
                kl[2*g][0] = r0; kl[2*g][1] = r2; kl[2*g+1][0] = r1; kl[2*g+1][1] = r3;
            }
#pragma unroll
            for (int j = 0; j < 8; j++) {
                mma16816(s[j], qh[ks], kb[j]);
                mma16816(s[j], qh[ks], kl[j]);
                mma16816(s[j], ql[ks], kb[j]);
            }
        }

        // online softmax
        const int c0 = (lane & 3) * 2;
        float mn0 = mi0, mn1 = mi1;
#pragma unroll
        for (int j = 0; j < 8; j++) {
            float mk0 = msk[st][j * 8 + c0], mk1 = msk[st][j * 8 + c0 + 1];
            s[j][0] += mk0; s[j][1] += mk1; s[j][2] += mk0; s[j][3] += mk1;
            mn0 = fmaxf(mn0, fmaxf(s[j][0], s[j][1]));
            mn1 = fmaxf(mn1, fmaxf(s[j][2], s[j][3]));
        }
        mn0 = fmaxf(mn0, __shfl_xor_sync(0xffffffffu, mn0, 1));
        mn0 = fmaxf(mn0, __shfl_xor_sync(0xffffffffu, mn0, 2));
        mn1 = fmaxf(mn1, __shfl_xor_sync(0xffffffffu, mn1, 1));
        mn1 = fmaxf(mn1, __shfl_xor_sync(0xffffffffu, mn1, 2));

        float a0 = __expf(mi0 - mn0), a1 = __expf(mi1 - mn1);
        float rs0 = 0.f, rs1 = 0.f;
        uint32_t pah[4][4], pal[4][4];
#pragma unroll
        for (int j = 0; j < 8; j++) {
            float p0 = __expf(s[j][0] - mn0), p1 = __expf(s[j][1] - mn0);
            float p2 = __expf(s[j][2] - mn1), p3 = __expf(s[j][3] - mn1);
            rs0 += p0 + p1; rs1 += p2 + p3;
            uint32_t h01, l01, h23, l23;
            splitpack2(p0, p1, h01, l01);
            splitpack2(p2, p3, h23, l23);
            pah[j >> 1][2*(j & 1) + 0] = h01; pah[j >> 1][2*(j & 1) + 1] = h23;
            pal[j >> 1][2*(j & 1) + 0] = l01; pal[j >> 1][2*(j & 1) + 1] = l23;
        }
        rs0 += __shfl_xor_sync(0xffffffffu, rs0, 1);
        rs0 += __shfl_xor_sync(0xffffffffu, rs0, 2);
        rs1 += __shfl_xor_sync(0xffffffffu, rs1, 1);
        rs1 += __shfl_xor_sync(0xffffffffu, rs1, 2);
        li0 = li0 * a0 + rs0; li1 = li1 * a1 + rs1;
        mi0 = mn0; mi1 = mn1;
#pragma unroll
        for (int j = 0; j < 8; j++) {
            o[j][0] *= a0; o[j][1] *= a0; o[j][2] *= a1; o[j][3] *= a1;
        }

        // O += P @ V
#pragma unroll
        for (int ks = 0; ks < 4; ks++) {
            uint32_t vb[8][2], vl[8][2];
#pragma unroll
            for (int dt = 0; dt < 4; dt++) {
                uint32_t off = SWZ((ks * 16 + (lane & 15)) * 128 + dt * 32 + csel);
                uint32_t r0, r1, r2, r3;
                LDSM4T(r0, r1, r2, r3, sVh + off);
                vb[2*dt][0] = r0; vb[2*dt][1] = r1; vb[2*dt+1][0] = r2; vb[2*dt+1][1] = r3;
                LDSM4T(r0, r1, r2, r3, sVl + off);
                vl[2*dt][0] = r0; vl[2*dt][1] = r1; vl[2*dt+1][0] = r2; vl[2*dt+1][1] = r3;
            }
#pragma unroll
            for (int j = 0; j < 8; j++) {
                mma16816(o[j], pah[ks], vb[j]);
                mma16816(o[j], pah[ks], vl[j]);
                mma16816(o[j], pal[ks], vb[j]);
            }
        }
        __syncthreads();
    }

    // epilogue: normalize, split to bf16 hi/lo, store [b][s][h][d]
    float inv0 = 1.f / li0, inv1 = 1.f / li1;
    int r0 = q0 + w * 16 + (lane >> 2);
#pragma unroll
    for (int j = 0; j < 8; j++) {
        int d = j * 8 + (lane & 3) * 2;
        float v0 = o[j][0] * inv0, v1 = o[j][1] * inv0;
        float v2 = o[j][2] * inv1, v3 = o[j][3] * inv1;
        uint32_t h01, l01, h23, l23;
        splitpack2(v0, v1, h01, l01);
        splitpack2(v2, v3, h23, l23);
        size_t i0 = (((size_t)bbi * SS + r0) * HH + hh) * DD + d;
        size_t i1 = (((size_t)bbi * SS + r0 + 8) * HH + hh) * DD + d;
        *(uint32_t*)&g_atthi[i0] = h01; *(uint32_t*)&g_attlo[i0] = l01;
        *(uint32_t*)&g_atthi[i1] = h23; *(uint32_t*)&g_attlo[i1] = l23;
    }
}

// ---------------------------------------------------------------------------
extern "C" void kernel_launch(void* const* d_in, const int* in_sizes, int n_in,
                              void* d_out, int out_size)
{
    const float* x     = (const float*)d_in[0];
    const int*   mask  = (const int*)  d_in[1];
    const float* qkv_w = (const float*)d_in[2];
    const float* out_w = (const float*)d_in[3];
    const float* out_b = (const float*)d_in[4];
    float*       out   = (float*)d_out;

    __nv_bfloat16 *xhi, *xlo, *wqhi, *wqlo, *wohi, *wolo, *athi, *atlo;
    cudaGetSymbolAddress((void**)&xhi,  g_xhi);  cudaGetSymbolAddress((void**)&xlo,  g_xlo);
    cudaGetSymbolAddress((void**)&wqhi, g_wqhi); cudaGetSymbolAddress((void**)&wqlo, g_wqlo);
    cudaGetSymbolAddress((void**)&wohi, g_wohi); cudaGetSymbolAddress((void**)&wolo, g_wolo);
    cudaGetSymbolAddress((void**)&athi, g_atthi); cudaGetSymbolAddress((void**)&atlo, g_attlo);

    cudaFuncSetAttribute(mm_mma,   cudaFuncAttributeMaxDynamicSharedMemorySize, GSMEM);
    cudaFuncSetAttribute(attn_mma, cudaFuncAttributeMaxDynamicSharedMemorySize, ASMEM);

    // 1) splits
    {
        int n4 = M1 * KDIM / 4;
        split_bf16<<<(n4 + 255) / 256, 256>>>(x, xhi, xlo, n4);
        n4 = N1 * KDIM / 4;
        split_bf16<<<(n4 + 255) / 256, 256>>>(qkv_w, wqhi, wqlo, n4);
        n4 = EE * KDIM / 4;
        split_bf16<<<(n4 + 255) / 256, 256>>>(out_w, wohi, wolo, n4);
    }

    // 2) QKV projection (HMMA), scatters bf16 hi/lo q/k/v (q pre-scaled)
    {
        dim3 grid(N1 / 128, M1 / 128);   // 24 x 32
        mm_mma<<<grid, 256, GSMEM>>>(xhi, xlo, wqhi, wqlo, nullptr, nullptr, 0);
    }

    // 3) attention (HMMA FA2)
    {
        dim3 grid(SS / 128, BB * HH);    // 16 x 32
        attn_mma<<<grid, 256, ASMEM>>>(mask);
    }

    // 4) output projection (HMMA) + bias
    {
        dim3 grid(EE / 128, M1 / 128);   // 8 x 32
        mm_mma<<<grid, 256, GSMEM>>>(athi, atlo, wohi, wolo, out, out_b, 1);
    }
}

// round 4
// speedup vs baseline: 3.2360x; 1.0313x over previous
#include <cuda_runtime.h>
#include <cuda_bf16.h>
#include <cstdint>

#define BB   2
#define SS   2048
#define EE   1024
#define HH   16
#define DD   64
#define M1   4096
#define N1   3072
#define KDIM 1024
#define SCALE 0.125f

// ---------------------------------------------------------------------------
// helpers
// ---------------------------------------------------------------------------
__device__ __forceinline__ uint32_t smem_u32(const void* p) {
    uint32_t a;
    asm("{ .reg .u64 t; cvta.to.shared.u64 t, %1; cvt.u32.u64 %0, t; }" : "=r"(a) : "l"(p));
    return a;
}
#define SWZ(x) ((x) ^ (((x) >> 3) & 0x70))

#define CP16(dst, src) \
    asm volatile("cp.async.cg.shared.global [%0], [%1], 16;" :: "r"(dst), "l"(src))
#define CP_COMMIT() asm volatile("cp.async.commit_group;" ::: "memory")
#define CP_WAIT(n)  asm volatile("cp.async.wait_group %0;" :: "n"(n) : "memory")

#define LDSM4(r0,r1,r2,r3,a) \
    asm volatile("ldmatrix.sync.aligned.m8n8.x4.shared.b16 {%0,%1,%2,%3}, [%4];" \
                 : "=r"(r0),"=r"(r1),"=r"(r2),"=r"(r3) : "r"(a))
#define LDSM4T(r0,r1,r2,r3,a) \
    asm volatile("ldmatrix.sync.aligned.m8n8.x4.trans.shared.b16 {%0,%1,%2,%3}, [%4];" \
                 : "=r"(r0),"=r"(r1),"=r"(r2),"=r"(r3) : "r"(a))

__device__ __forceinline__ void mma16816(float* d, const uint32_t* a, const uint32_t* b) {
    asm volatile(
        "mma.sync.aligned.m16n8k16.row.col.f32.bf16.bf16.f32 "
        "{%0,%1,%2,%3}, {%4,%5,%6,%7}, {%8,%9}, {%0,%1,%2,%3};"
        : "+f"(d[0]), "+f"(d[1]), "+f"(d[2]), "+f"(d[3])
        : "r"(a[0]), "r"(a[1]), "r"(a[2]), "r"(a[3]), "r"(b[0]), "r"(b[1]));
}

__device__ __forceinline__ uint32_t packbf(__nv_bfloat16 a, __nv_bfloat16 b) {
    __nv_bfloat162 t; t.x = a; t.y = b;
    return *reinterpret_cast<uint32_t*>(&t);
}
__device__ __forceinline__ void splitpack2(float v0, float v1, uint32_t& hi, uint32_t& lo) {
    __nv_bfloat16 h0 = __float2bfloat16(v0), h1 = __float2bfloat16(v1);
    __nv_bfloat16 l0 = __float2bfloat16(v0 - __bfloat162float(h0));
    __nv_bfloat16 l1 = __float2bfloat16(v1 - __bfloat162float(h1));
    hi = packbf(h0, h1); lo = packbf(l0, l1);
}

// ---------------------------------------------------------------------------
// scratch (__device__ globals)
// ---------------------------------------------------------------------------
#define QKV_ELEMS ((size_t)BB*HH*SS*DD)
__device__ __nv_bfloat16 g_qhi[QKV_ELEMS], g_qlo[QKV_ELEMS];
__device__ __nv_bfloat16 g_khi[QKV_ELEMS], g_klo[QKV_ELEMS];
__device__ __nv_bfloat16 g_vhi[QKV_ELEMS], g_vlo[QKV_ELEMS];
__device__ __nv_bfloat16 g_xhi[(size_t)M1*KDIM],  g_xlo[(size_t)M1*KDIM];
__device__ __nv_bfloat16 g_wqhi[(size_t)N1*KDIM], g_wqlo[(size_t)N1*KDIM];
__device__ __nv_bfloat16 g_wohi[(size_t)EE*KDIM], g_wolo[(size_t)EE*KDIM];
__device__ __nv_bfloat16 g_atthi[(size_t)M1*EE],  g_attlo[(size_t)M1*EE];

// ---------------------------------------------------------------------------
// fp32 -> bf16 hi/lo split
// ---------------------------------------------------------------------------
__global__ __launch_bounds__(256) void split_bf16(const float* __restrict__ in,
                                                  __nv_bfloat16* __restrict__ hi,
                                                  __nv_bfloat16* __restrict__ lo,
                                                  int n4)
{
    int i = blockIdx.x * blockDim.x + threadIdx.x;
    if (i >= n4) return;
    float4 v = ((const float4*)in)[i];
    uint32_t h01, l01, h23, l23;
    splitpack2(v.x, v.y, h01, l01);
    splitpack2(v.z, v.w, h23, l23);
    ((uint2*)hi)[i] = make_uint2(h01, h23);
    ((uint2*)lo)[i] = make_uint2(l01, l23);
}

// ---------------------------------------------------------------------------
// HMMA GEMM: C[M,N] = (Ahi+Alo)[M,K] @ (Bhi+Blo)[N,K]^T  (3-term split)
// 128x128 tile, 8 warps (64x32 warp tiles), K chunks of 64.
// 3-stage cp.async pipeline, ONE __syncthreads per chunk.
// ---------------------------------------------------------------------------
#define GSTG 65536
#define GSMEM (3*GSTG)

__global__ __launch_bounds__(256, 1) void mm_mma(
    const __nv_bfloat16* __restrict__ Ahi, const __nv_bfloat16* __restrict__ Alo,
    const __nv_bfloat16* __restrict__ Bhi, const __nv_bfloat16* __restrict__ Blo,
    float* __restrict__ Cout, const float* __restrict__ bias, int mode)
{
    extern __shared__ char smc[];
    const int tid = threadIdx.x, lane = tid & 31, w = tid >> 5;
    const int wr = w >> 2, wc = w & 3;
    const int bm = blockIdx.y * 128, bn = blockIdx.x * 128;
    const uint32_t smb = smem_u32(smc);

    auto load_stage = [&](int st, int ch) {
        const int koff = ch * 64;
#pragma unroll
        for (int t = 0; t < 4; t++) {
            const __nv_bfloat16* src = (t == 0) ? Ahi : (t == 1) ? Alo : (t == 2) ? Bhi : Blo;
            const int row0 = (t < 2) ? bm : bn;
#pragma unroll
            for (int i = 0; i < 4; i++) {
                int cid = tid + i * 256;
                int r = cid >> 3, c = cid & 7;
                uint32_t sa = smb + st * GSTG + t * 16384 + SWZ(r * 128 + c * 16);
                const char* ga = (const char*)(src + (size_t)(row0 + r) * KDIM + koff) + c * 16;
                CP16(sa, ga);
            }
        }
    };

    float acc[4][4][4];
#pragma unroll
    for (int i = 0; i < 4; i++)
#pragma unroll
        for (int j = 0; j < 4; j++)
#pragma unroll
            for (int q = 0; q < 4; q++) acc[i][j][q] = 0.f;

    load_stage(0, 0); CP_COMMIT();
    load_stage(1, 1); CP_COMMIT();

    const int aro  = (lane & 7) + 8 * ((lane >> 3) & 1);
    const int csel = 16 * (lane >> 4);

    for (int ch = 0; ch < 16; ch++) {
        const int st = ch % 3;
        if (ch < 15) { CP_WAIT(1); } else { CP_WAIT(0); }
        __syncthreads();
        // prefetch chunk ch+2 into stage (ch+2)%3 (== stage of ch-1, safe after barrier)
        if (ch + 2 < 16) { load_stage((ch + 2) % 3, ch + 2); CP_COMMIT(); }

        const uint32_t sAh = smb + st * GSTG;
        const uint32_t sAl = sAh + 16384;
        const uint32_t sBh = sAh + 32768;
        const uint32_t sBl = sAh + 49152;

#pragma unroll
        for (int ks = 0; ks < 4; ks++) {
            const int colb = ks * 32 + csel;
            uint32_t ah[4][4], al[4][4];
#pragma unroll
            for (int i = 0; i < 4; i++) {
                uint32_t off = SWZ((wr * 64 + i * 16 + aro) * 128 + colb);
                LDSM4(ah[i][0], ah[i][1], ah[i][2], ah[i][3], sAh + off);
                LDSM4(al[i][0], al[i][1], al[i][2], al[i][3], sAl + off);
            }
            uint32_t bhf[4][2], blf[4][2];
#pragma unroll
            for (int g = 0; g < 2; g++) {
                uint32_t off = SWZ((wc * 32 + g * 16 + aro) * 128 + colb);
                uint32_t r0, r1, r2, r3;
                LDSM4(r0, r1, r2, r3, sBh + off);
                bhf[2*g][0] = r0; bhf[2*g][1] = r2; bhf[2*g+1][0] = r1; bhf[2*g+1][1] = r3;
                LDSM4(r0, r1, r2, r3, sBl + off);
                blf[2*g][0] = r0; blf[2*g][1] = r2; blf[2*g+1][0] = r1; blf[2*g+1][1] = r3;
            }
#pragma unroll
            for (int i = 0; i < 4; i++)
#pragma unroll
                for (int j = 0; j < 4; j++) {
                    mma16816(acc[i][j], ah[i], bhf[j]);
                    mma16816(acc[i][j], ah[i], blf[j]);
                    mma16816(acc[i][j], al[i], bhf[j]);
                }
        }
    }

    // epilogue
#pragma unroll
    for (int i = 0; i < 4; i++) {
        int mrow = bm + wr * 64 + i * 16 + (lane >> 2);
#pragma unroll
        for (int j = 0; j < 4; j++) {
            int n = bn + wc * 32 + j * 8 + (lane & 3) * 2;
            if (mode == 0) {
                int c = n >> 10, h = (n >> 6) & 15, d = n & 63;
                float sc = (c == 0) ? SCALE : 1.0f;
                __nv_bfloat16* dh = (c == 0) ? g_qhi : (c == 1) ? g_khi : g_vhi;
                __nv_bfloat16* dl = (c == 0) ? g_qlo : (c == 1) ? g_klo : g_vlo;
#pragma unroll
                for (int rr = 0; rr < 2; rr++) {
                    int m = mrow + rr * 8;
                    int b = m >> 11, s = m & 2047;
                    float v0 = acc[i][j][2*rr + 0] * sc;
                    float v1 = acc[i][j][2*rr + 1] * sc;
                    uint32_t hi, lo;
                    splitpack2(v0, v1, hi, lo);
                    size_t idx = (((size_t)b * HH + h) * SS + s) * DD + d;
                    *(uint32_t*)&dh[idx] = hi;
                    *(uint32_t*)&dl[idx] = lo;
                }
            } else {
                float2 b2 = *(const float2*)&bias[n];
                float2 o0 = make_float2(acc[i][j][0] + b2.x, acc[i][j][1] + b2.y);
                float2 o1 = make_float2(acc[i][j][2] + b2.x, acc[i][j][3] + b2.y);
                *(float2*)&Cout[(size_t)mrow * EE + n] = o0;
                *(float2*)&Cout[(size_t)(mrow + 8) * EE + n] = o1;
            }
        }
    }
}

// ---------------------------------------------------------------------------
// FA2-style HMMA attention. CTA = (b,h) x 128 q-rows; 8 warps, 16 rows each.
// KV tiles of 64 keys, 3-stage cp.async pipeline, ONE sync per tile.
// ---------------------------------------------------------------------------
#define AKV0 32768
#define ASTG 32768
#define ASMEM (AKV0 + 3*ASTG)   // 128 KB

__global__ __launch_bounds__(256, 1) void attn_mma(const int* __restrict__ mask)
{
    extern __shared__ char smc[];
    __shared__ float msk[3][64];
    const int tid = threadIdx.x, lane = tid & 31, w = tid >> 5;
    const int bh = blockIdx.y, bbi = bh >> 4, hh = bh & 15;
    const int q0 = blockIdx.x * 128;
    const uint32_t smb = smem_u32(smc);
    const uint32_t sQh = smb, sQl = smb + 16384;

    const size_t bhoff = (size_t)bh * SS * DD;
    const __nv_bfloat16* Khg = g_khi + bhoff;
    const __nv_bfloat16* Klg = g_klo + bhoff;
    const __nv_bfloat16* Vhg = g_vhi + bhoff;
    const __nv_bfloat16* Vlg = g_vlo + bhoff;
    const __nv_bfloat16* Qhg = g_qhi + bhoff + (size_t)q0 * DD;
    const __nv_bfloat16* Qlg = g_qlo + bhoff + (size_t)q0 * DD;

    // Q tile: 128 x 64 bf16, hi+lo (own commit group)
#pragma unroll
    for (int i = 0; i < 4; i++) {
        int cid = tid + i * 256;
        int r = cid >> 3, c = cid & 7;
        uint32_t so = SWZ(r * 128 + c * 16);
        CP16(sQh + so, (const char*)(Qhg + (size_t)r * DD) + c * 16);
        CP16(sQl + so, (const char*)(Qlg + (size_t)r * DD) + c * 16);
    }
    CP_COMMIT();

    auto load_kv = [&](int st, int kt) {
        uint32_t base = smb + AKV0 + st * ASTG;
        const int s0 = kt * 64;
#pragma unroll
        for (int i = 0; i < 2; i++) {
            int cid = tid + i * 256;
            int r = cid >> 3, c = cid & 7;
            uint32_t so = SWZ(r * 128 + c * 16);
            size_t go = (size_t)(s0 + r) * DD;
            CP16(base + so,         (const char*)(Khg + go) + c * 16);
            CP16(base + 8192 + so,  (const char*)(Klg + go) + c * 16);
            CP16(base + 16384 + so, (const char*)(Vhg + go) + c * 16);
            CP16(base + 24576 + so, (const char*)(Vlg + go) + c * 16);
        }
    };
    load_kv(0, 0); CP_COMMIT();
    load_kv(1, 1); CP_COMMIT();
    if (tid < 64) {
        msk[0][tid] = mask[bbi * SS + tid] ? 0.f : -1e30f;
        msk[1][tid] = mask[bbi * SS + 64 + tid] ? 0.f : -1e30f;
    }
    CP_WAIT(2);       // Q arrived (kv0, kv1 may still be in flight)
    __syncthreads();

    const int aro  = (lane & 7) + 8 * ((lane >> 3) & 1);
    const int csel = 16 * (lane >> 4);

    // Q fragments (persist in registers)
    uint32_t qh[4][4], ql[4][4];
#pragma unroll
    for (int ks = 0; ks < 4; ks++) {
        uint32_t off = SWZ((w * 16 + aro) * 128 + ks * 32 + csel);
        LDSM4(qh[ks][0], qh[ks][1], qh[ks][2], qh[ks][3], sQh + off);
        LDSM4(ql[ks][0], ql[ks][1], ql[ks][2], ql[ks][3], sQl + off);
    }

    float o[8][4];
#pragma unroll
    for (int j = 0; j < 8; j++)
#pragma unroll
        for (int q = 0; q < 4; q++) o[j][q] = 0.f;
    float mi0 = -1e30f, mi1 = -1e30f, li0 = 0.f, li1 = 0.f;

    for (int kt = 0; kt < 32; kt++) {
        const int st = kt % 3;
        if (kt < 31) { CP_WAIT(1); } else { CP_WAIT(0); }
        __syncthreads();
        if (kt + 2 < 32) {
            load_kv((kt + 2) % 3, kt + 2); CP_COMMIT();
            if (tid < 64)
                msk[(kt + 2) % 3][tid] = mask[bbi * SS + (kt + 2) * 64 + tid] ? 0.f : -1e30f;
        }

        const uint32_t sKh = smb + AKV0 + st * ASTG;
        const uint32_t sKl = sKh + 8192;
        const uint32_t sVh = sKh + 16384;
        const uint32_t sVl = sKh + 24576;

        // S = Q @ K^T (Q pre-scaled)
        float s[8][4];
#pragma unroll
        for (int j = 0; j < 8; j++)
#pragma unroll
            for (int q = 0; q < 4; q++) s[j][q] = 0.f;
#pragma unroll
        for (int ks = 0; ks < 4; ks++) {
            const int colb = ks * 32 + csel;
            uint32_t kb[8][2], kl[8][2];
#pragma unroll
            for (int g = 0; g < 4; g++) {
                uint32_t off = SWZ((g * 16 + aro) * 128 + colb);
                uint32_t r0, r1, r2, r3;
                LDSM4(r0, r1, r2, r3, sKh + off);
                kb[2*g][0] = r0; kb[2*g][1] = r2; kb[2*g+1][0] = r1; kb[2*g+1][1] = r3;
                LDSM4(r0, r1, r2, r3, sKl + off);
                kl[2*g][0] = r0; kl[2*g][1] = r2; kl[2*g+1][0] = r1; kl[2*g+1][1] = r3;
            }
#pragma unroll
            for (int j = 0; j < 8; j++) {
                mma16816(s[j], qh[ks], kb[j]);
                mma16816(s[j], qh[ks], kl[j]);
                mma16816(s[j], ql[ks], kb[j]);
            }
        }

        // online softmax
        const int c0 = (lane & 3) * 2;
        float mn0 = mi0, mn1 = mi1;
#pragma unroll
        for (int j = 0; j < 8; j++) {
            float mk0 = msk[st][j * 8 + c0], mk1 = msk[st][j * 8 + c0 + 1];
            s[j][0] += mk0; s[j][1] += mk1; s[j][2] += mk0; s[j][3] += mk1;
            mn0 = fmaxf(mn0, fmaxf(s[j][0], s[j][1]));
            mn1 = fmaxf(mn1, fmaxf(s[j][2], s[j][3]));
        }
        mn0 = fmaxf(mn0, __shfl_xor_sync(0xffffffffu, mn0, 1));
        mn0 = fmaxf(mn0, __shfl_xor_sync(0xffffffffu, mn0, 2));
        mn1 = fmaxf(mn1, __shfl_xor_sync(0xffffffffu, mn1, 1));
        mn1 = fmaxf(mn1, __shfl_xor_sync(0xffffffffu, mn1, 2));

        float a0 = __expf(mi0 - mn0), a1 = __expf(mi1 - mn1);
        float rs0 = 0.f, rs1 = 0.f;
        uint32_t pah[4][4], pal[4][4];
#pragma unroll
        for (int j = 0; j < 8; j++) {
            float p0 = __expf(s[j][0] - mn0), p1 = __expf(s[j][1] - mn0);
            float p2 = __expf(s[j][2] - mn1), p3 = __expf(s[j][3] - mn1);
            rs0 += p0 + p1; rs1 += p2 + p3;
            uint32_t h01, l01, h23, l23;
            splitpack2(p0, p1, h01, l01);
            splitpack2(p2, p3, h23, l23);
            pah[j >> 1][2*(j & 1) + 0] = h01; pah[j >> 1][2*(j & 1) + 1] = h23;
            pal[j >> 1][2*(j & 1) + 0] = l01; pal[j >> 1][2*(j & 1) + 1] = l23;
        }
        rs0 += __shfl_xor_sync(0xffffffffu, rs0, 1);
        rs0 += __shfl_xor_sync(0xffffffffu, rs0, 2);
        rs1 += __shfl_xor_sync(0xffffffffu, rs1, 1);
        rs1 += __shfl_xor_sync(0xffffffffu, rs1, 2);
        li0 = li0 * a0 + rs0; li1 = li1 * a1 + rs1;
        mi0 = mn0; mi1 = mn1;
#pragma unroll
        for (int j = 0; j < 8; j++) {
            o[j][0] *= a0; o[j][1] *= a0; o[j][2] *= a1; o[j][3] *= a1;
        }

        // O += P @ V
#pragma unroll
        for (int ks = 0; ks < 4; ks++) {
            uint32_t vb[8][2], vl[8][2];
#pragma unroll
            for (int dt = 0; dt < 4; dt++) {
                uint32_t off = SWZ((ks * 16 + (lane & 15)) * 128 + dt * 32 + csel);
                uint32_t r0, r1, r2, r3;
                LDSM4T(r0, r1, r2, r3, sVh + off);
                vb[2*dt][0] = r0; vb[2*dt][1] = r1; vb[2*dt+1][0] = r2; vb[2*dt+1][1] = r3;
                LDSM4T(r0, r1, r2, r3, sVl + off);
                vl[2*dt][0] = r0; vl[2*dt][1] = r1; vl[2*dt+1][0] = r2; vl[2*dt+1][1] = r3;
            }
#pragma unroll
            for (int j = 0; j < 8; j++) {
                mma16816(o[j], pah[ks], vb[j]);
                mma16816(o[j], pah[ks], vl[j]);
                mma16816(o[j], pal[ks], vb[j]);
            }
        }
    }

    // epilogue: normalize, split to bf16 hi/lo, store [b][s][h][d]
    float inv0 = 1.f / li0, inv1 = 1.f / li1;
    int r0 = q0 + w * 16 + (lane >> 2);
#pragma unroll
    for (int j = 0; j < 8; j++) {
        int d = j * 8 + (lane & 3) * 2;
        float v0 = o[j][0] * inv0, v1 = o[j][1] * inv0;
        float v2 = o[j][2] * inv1, v3 = o[j][3] * inv1;
        uint32_t h01, l01, h23, l23;
        splitpack2(v0, v1, h01, l01);
        splitpack2(v2, v3, h23, l23);
        size_t i0 = (((size_t)bbi * SS + r0) * HH + hh) * DD + d;
        size_t i1 = (((size_t)bbi * SS + r0 + 8) * HH + hh) * DD + d;
        *(uint32_t*)&g_atthi[i0] = h01; *(uint32_t*)&g_attlo[i0] = l01;
        *(uint32_t*)&g_atthi[i1] = h23; *(uint32_t*)&g_attlo[i1] = l23;
    }
}

// ---------------------------------------------------------------------------
extern "C" void kernel_launch(void* const* d_in, const int* in_sizes, int n_in,
                              void* d_out, int out_size)
{
    const float* x     = (const float*)d_in[0];
    const int*   mask  = (const int*)  d_in[1];
    const float* qkv_w = (const float*)d_in[2];
    const float* out_w = (const float*)d_in[3];
    const float* out_b = (const float*)d_in[4];
    float*       out   = (float*)d_out;

    __nv_bfloat16 *xhi, *xlo, *wqhi, *wqlo, *wohi, *wolo, *athi, *atlo;
    cudaGetSymbolAddress((void**)&xhi,  g_xhi);  cudaGetSymbolAddress((void**)&xlo,  g_xlo);
    cudaGetSymbolAddress((void**)&wqhi, g_wqhi); cudaGetSymbolAddress((void**)&wqlo, g_wqlo);
    cudaGetSymbolAddress((void**)&wohi, g_wohi); cudaGetSymbolAddress((void**)&wolo, g_wolo);
    cudaGetSymbolAddress((void**)&athi, g_atthi); cudaGetSymbolAddress((void**)&atlo, g_attlo);

    cudaFuncSetAttribute(mm_mma,   cudaFuncAttributeMaxDynamicSharedMemorySize, GSMEM);
    cudaFuncSetAttribute(attn_mma, cudaFuncAttributeMaxDynamicSharedMemorySize, ASMEM);

    // 1) splits
    {
        int n4 = M1 * KDIM / 4;
        split_bf16<<<(n4 + 255) / 256, 256>>>(x, xhi, xlo, n4);
        n4 = N1 * KDIM / 4;
        split_bf16<<<(n4 + 255) / 256, 256>>>(qkv_w, wqhi, wqlo, n4);
        n4 = EE * KDIM / 4;
        split_bf16<<<(n4 + 255) / 256, 256>>>(out_w, wohi, wolo, n4);
    }

    // 2) QKV projection (HMMA), scatters bf16 hi/lo q/k/v (q pre-scaled)
    {
        dim3 grid(N1 / 128, M1 / 128);   // 24 x 32
        mm_mma<<<grid, 256, GSMEM>>>(xhi, xlo, wqhi, wqlo, nullptr, nullptr, 0);
    }

    // 3) attention (HMMA FA2)
    {
        dim3 grid(SS / 128, BB * HH);    // 16 x 32
        attn_mma<<<grid, 256, ASMEM>>>(mask);
    }

    // 4) output projection (HMMA) + bias
    {
        dim3 grid(EE / 128, M1 / 128);   // 8 x 32
        mm_mma<<<grid, 256, GSMEM>>>(athi, atlo, wohi, wolo, out, out_b, 1);
    }
}

// round 5
// speedup vs baseline: 3.3253x; 1.0276x over previous
#include <cuda_runtime.h>
#include <cuda_bf16.h>
#include <cstdint>

#define BB   2
#define SS   2048
#define EE   1024
#define HH   16
#define DD   64
#define M1   4096
#define N1   3072
#define KDIM 1024
#define SCALE 0.125f

// ---------------------------------------------------------------------------
// helpers
// ---------------------------------------------------------------------------
__device__ __forceinline__ uint32_t smem_u32(const void* p) {
    uint32_t a;
    asm("{ .reg .u64 t; cvta.to.shared.u64 t, %1; cvt.u32.u64 %0, t; }" : "=r"(a) : "l"(p));
    return a;
}
#define SWZ(x) ((x) ^ (((x) >> 3) & 0x70))

#define CP16(dst, src) \
    asm volatile("cp.async.cg.shared.global [%0], [%1], 16;" :: "r"(dst), "l"(src))
#define CP_COMMIT() asm volatile("cp.async.commit_group;" ::: "memory")
#define CP_WAIT(n)  asm volatile("cp.async.wait_group %0;" :: "n"(n) : "memory")

#define LDSM4(r0,r1,r2,r3,a) \
    asm volatile("ldmatrix.sync.aligned.m8n8.x4.shared.b16 {%0,%1,%2,%3}, [%4];" \
                 : "=r"(r0),"=r"(r1),"=r"(r2),"=r"(r3) : "r"(a))
#define LDSM4T(r0,r1,r2,r3,a) \
    asm volatile("ldmatrix.sync.aligned.m8n8.x4.trans.shared.b16 {%0,%1,%2,%3}, [%4];" \
                 : "=r"(r0),"=r"(r1),"=r"(r2),"=r"(r3) : "r"(a))

__device__ __forceinline__ void mma16816(float* d, const uint32_t* a, const uint32_t* b) {
    asm volatile(
        "mma.sync.aligned.m16n8k16.row.col.f32.bf16.bf16.f32 "
        "{%0,%1,%2,%3}, {%4,%5,%6,%7}, {%8,%9}, {%0,%1,%2,%3};"
        : "+f"(d[0]), "+f"(d[1]), "+f"(d[2]), "+f"(d[3])
        : "r"(a[0]), "r"(a[1]), "r"(a[2]), "r"(a[3]), "r"(b[0]), "r"(b[1]));
}

__device__ __forceinline__ uint32_t packbf(__nv_bfloat16 a, __nv_bfloat16 b) {
    __nv_bfloat162 t; t.x = a; t.y = b;
    return *reinterpret_cast<uint32_t*>(&t);
}
__device__ __forceinline__ void splitpack2(float v0, float v1, uint32_t& hi, uint32_t& lo) {
    __nv_bfloat16 h0 = __float2bfloat16(v0), h1 = __float2bfloat16(v1);
    __nv_bfloat16 l0 = __float2bfloat16(v0 - __bfloat162float(h0));
    __nv_bfloat16 l1 = __float2bfloat16(v1 - __bfloat162float(h1));
    hi = packbf(h0, h1); lo = packbf(l0, l1);
}

// ---------------------------------------------------------------------------
// scratch (__device__ globals)
// ---------------------------------------------------------------------------
#define QKV_ELEMS ((size_t)BB*HH*SS*DD)
__device__ __nv_bfloat16 g_qhi[QKV_ELEMS], g_qlo[QKV_ELEMS];
__device__ __nv_bfloat16 g_khi[QKV_ELEMS], g_klo[QKV_ELEMS];
__device__ __nv_bfloat16 g_vhi[QKV_ELEMS], g_vlo[QKV_ELEMS];
__device__ __nv_bfloat16 g_xhi[(size_t)M1*KDIM],  g_xlo[(size_t)M1*KDIM];
__device__ __nv_bfloat16 g_wqhi[(size_t)N1*KDIM], g_wqlo[(size_t)N1*KDIM];
__device__ __nv_bfloat16 g_wohi[(size_t)EE*KDIM], g_wolo[(size_t)EE*KDIM];
__device__ __nv_bfloat16 g_atthi[(size_t)M1*EE],  g_attlo[(size_t)M1*EE];

// ---------------------------------------------------------------------------
// fp32 -> bf16 hi/lo split
// ---------------------------------------------------------------------------
__global__ __launch_bounds__(256) void split_bf16(const float* __restrict__ in,
                                                  __nv_bfloat16* __restrict__ hi,
                                                  __nv_bfloat16* __restrict__ lo,
                                                  int n4)
{
    int i = blockIdx.x * blockDim.x + threadIdx.x;
    if (i >= n4) return;
    float4 v = ((const float4*)in)[i];
    uint32_t h01, l01, h23, l23;
    splitpack2(v.x, v.y, h01, l01);
    splitpack2(v.z, v.w, h23, l23);
    ((uint2*)hi)[i] = make_uint2(h01, h23);
    ((uint2*)lo)[i] = make_uint2(l01, l23);
}

// ---------------------------------------------------------------------------
// HMMA GEMM: C[M,N] = (Ahi+Alo)[M,K] @ (Bhi+Blo)[N,K]^T  (3-term split)
// 128x128 tile, 16 warps (32x32 warp tiles), 512 threads -> 4 warps/SMSP.
// K chunks of 64, 3-stage cp.async pipeline, one sync per chunk.
// ---------------------------------------------------------------------------
#define GSTG 65536
#define GSMEM (3*GSTG)

__global__ __launch_bounds__(512, 1) void mm_mma(
    const __nv_bfloat16* __restrict__ Ahi, const __nv_bfloat16* __restrict__ Alo,
    const __nv_bfloat16* __restrict__ Bhi, const __nv_bfloat16* __restrict__ Blo,
    float* __restrict__ Cout, const float* __restrict__ bias, int mode)
{
    extern __shared__ char smc[];
    const int tid = threadIdx.x, lane = tid & 31, w = tid >> 5;
    const int wr = w >> 2, wc = w & 3;           // 4x4 warp grid, 32x32 tiles
    const int bm = blockIdx.y * 128, bn = blockIdx.x * 128;
    const uint32_t smb = smem_u32(smc);

    auto load_stage = [&](int st, int ch) {
        const int koff = ch * 64;
#pragma unroll
        for (int t = 0; t < 4; t++) {
            const __nv_bfloat16* src = (t == 0) ? Ahi : (t == 1) ? Alo : (t == 2) ? Bhi : Blo;
            const int row0 = (t < 2) ? bm : bn;
#pragma unroll
            for (int i = 0; i < 2; i++) {
                int cid = tid + i * 512;             // 0..1023
                int r = cid >> 3, c = cid & 7;
                uint32_t sa = smb + st * GSTG + t * 16384 + SWZ(r * 128 + c * 16);
                const char* ga = (const char*)(src + (size_t)(row0 + r) * KDIM + koff) + c * 16;
                CP16(sa, ga);
            }
        }
    };

    float acc[2][4][4];
#pragma unroll
    for (int i = 0; i < 2; i++)
#pragma unroll
        for (int j = 0; j < 4; j++)
#pragma unroll
            for (int q = 0; q < 4; q++) acc[i][j][q] = 0.f;

    load_stage(0, 0); CP_COMMIT();
    load_stage(1, 1); CP_COMMIT();

    const int aro  = (lane & 7) + 8 * ((lane >> 3) & 1);
    const int csel = 16 * (lane >> 4);

    for (int ch = 0; ch < 16; ch++) {
        const int st = ch % 3;
        if (ch < 15) { CP_WAIT(1); } else { CP_WAIT(0); }
        __syncthreads();
        if (ch + 2 < 16) { load_stage((ch + 2) % 3, ch + 2); CP_COMMIT(); }

        const uint32_t sAh = smb + st * GSTG;
        const uint32_t sAl = sAh + 16384;
        const uint32_t sBh = sAh + 32768;
        const uint32_t sBl = sAh + 49152;

#pragma unroll
        for (int ks = 0; ks < 4; ks++) {
            const int colb = ks * 32 + csel;
            uint32_t ah[2][4], al[2][4];
#pragma unroll
            for (int i = 0; i < 2; i++) {
                uint32_t off = SWZ((wr * 32 + i * 16 + aro) * 128 + colb);
                LDSM4(ah[i][0], ah[i][1], ah[i][2], ah[i][3], sAh + off);
                LDSM4(al[i][0], al[i][1], al[i][2], al[i][3], sAl + off);
            }
            uint32_t bhf[4][2], blf[4][2];
#pragma unroll
            for (int g = 0; g < 2; g++) {
                uint32_t off = SWZ((wc * 32 + g * 16 + aro) * 128 + colb);
                uint32_t r0, r1, r2, r3;
                LDSM4(r0, r1, r2, r3, sBh + off);
                bhf[2*g][0] = r0; bhf[2*g][1] = r2; bhf[2*g+1][0] = r1; bhf[2*g+1][1] = r3;
                LDSM4(r0, r1, r2, r3, sBl + off);
                blf[2*g][0] = r0; blf[2*g][1] = r2; blf[2*g+1][0] = r1; blf[2*g+1][1] = r3;
            }
#pragma unroll
            for (int i = 0; i < 2; i++)
#pragma unroll
                for (int j = 0; j < 4; j++) {
                    mma16816(acc[i][j], ah[i], bhf[j]);
                    mma16816(acc[i][j], ah[i], blf[j]);
                    mma16816(acc[i][j], al[i], bhf[j]);
                }
        }
    }

    // epilogue
#pragma unroll
    for (int i = 0; i < 2; i++) {
        int mrow = bm + wr * 32 + i * 16 + (lane >> 2);
#pragma unroll
        for (int j = 0; j < 4; j++) {
            int n = bn + wc * 32 + j * 8 + (lane & 3) * 2;
            if (mode == 0) {
                int c = n >> 10, h = (n >> 6) & 15, d = n & 63;
                float sc = (c == 0) ? SCALE : 1.0f;
                __nv_bfloat16* dh = (c == 0) ? g_qhi : (c == 1) ? g_khi : g_vhi;
                __nv_bfloat16* dl = (c == 0) ? g_qlo : (c == 1) ? g_klo : g_vlo;
#pragma unroll
                for (int rr = 0; rr < 2; rr++) {
                    int m = mrow + rr * 8;
                    int b = m >> 11, s = m & 2047;
                    float v0 = acc[i][j][2*rr + 0] * sc;
                    float v1 = acc[i][j][2*rr + 1] * sc;
                    uint32_t hi, lo;
                    splitpack2(v0, v1, hi, lo);
                    size_t idx = (((size_t)b * HH + h) * SS + s) * DD + d;
                    *(uint32_t*)&dh[idx] = hi;
                    *(uint32_t*)&dl[idx] = lo;
                }
            } else {
                float2 b2 = *(const float2*)&bias[n];
                float2 o0 = make_float2(acc[i][j][0] + b2.x, acc[i][j][1] + b2.y);
                float2 o1 = make_float2(acc[i][j][2] + b2.x, acc[i][j][3] + b2.y);
                *(float2*)&Cout[(size_t)mrow * EE + n] = o0;
                *(float2*)&Cout[(size_t)(mrow + 8) * EE + n] = o1;
            }
        }
    }
}

// ---------------------------------------------------------------------------
// FA2-style HMMA attention (unchanged from round 4).
// ---------------------------------------------------------------------------
#define AKV0 32768
#define ASTG 32768
#define ASMEM (AKV0 + 3*ASTG)   // 128 KB

__global__ __launch_bounds__(256, 1) void attn_mma(const int* __restrict__ mask)
{
    extern __shared__ char smc[];
    __shared__ float msk[3][64];
    const int tid = threadIdx.x, lane = tid & 31, w = tid >> 5;
    const int bh = blockIdx.y, bbi = bh >> 4, hh = bh & 15;
    const int q0 = blockIdx.x * 128;
    const uint32_t smb = smem_u32(smc);
    const uint32_t sQh = smb, sQl = smb + 16384;

    const size_t bhoff = (size_t)bh * SS * DD;
    const __nv_bfloat16* Khg = g_khi + bhoff;
    const __nv_bfloat16* Klg = g_klo + bhoff;
    const __nv_bfloat16* Vhg = g_vhi + bhoff;
    const __nv_bfloat16* Vlg = g_vlo + bhoff;
    const __nv_bfloat16* Qhg = g_qhi + bhoff + (size_t)q0 * DD;
    const __nv_bfloat16* Qlg = g_qlo + bhoff + (size_t)q0 * DD;

#pragma unroll
    for (int i = 0; i < 4; i++) {
        int cid = tid + i * 256;
        int r = cid >> 3, c = cid & 7;
        uint32_t so = SWZ(r * 128 + c * 16);
        CP16(sQh + so, (const char*)(Qhg + (size_t)r * DD) + c * 16);
        CP16(sQl + so, (const char*)(Qlg + (size_t)r * DD) + c * 16);
    }
    CP_COMMIT();

    auto load_kv = [&](int st, int kt) {
        uint32_t base = smb + AKV0 + st * ASTG;
        const int s0 = kt * 64;
#pragma unroll
        for (int i = 0; i < 2; i++) {
            int cid = tid + i * 256;
            int r = cid >> 3, c = cid & 7;
            uint32_t so = SWZ(r * 128 + c * 16);
            size_t go = (size_t)(s0 + r) * DD;
            CP16(base + so,         (const char*)(Khg + go) + c * 16);
            CP16(base + 8192 + so,  (const char*)(Klg + go) + c * 16);
            CP16(base + 16384 + so, (const char*)(Vhg + go) + c * 16);
            CP16(base + 24576 + so, (const char*)(Vlg + go) + c * 16);
        }
    };
    load_kv(0, 0); CP_COMMIT();
    load_kv(1, 1); CP_COMMIT();
    if (tid < 64) {
        msk[0][tid] = mask[bbi * SS + tid] ? 0.f : -1e30f;
        msk[1][tid] = mask[bbi * SS + 64 + tid] ? 0.f : -1e30f;
    }
    CP_WAIT(2);
    __syncthreads();

    const int aro  = (lane & 7) + 8 * ((lane >> 3) & 1);
    const int csel = 16 * (lane >> 4);

    uint32_t qh[4][4], ql[4][4];
#pragma unroll
    for (int ks = 0; ks < 4; ks++) {
        uint32_t off = SWZ((w * 16 + aro) * 128 + ks * 32 + csel);
        LDSM4(qh[ks][0], qh[ks][1], qh[ks][2], qh[ks][3], sQh + off);
        LDSM4(ql[ks][0], ql[ks][1], ql[ks][2], ql[ks][3], sQl + off);
    }

    float o[8][4];
#pragma unroll
    for (int j = 0; j < 8; j++)
#pragma unroll
        for (int q = 0; q < 4; q++) o[j][q] = 0.f;
    float mi0 = -1e30f, mi1 = -1e30f, li0 = 0.f, li1 = 0.f;

    for (int kt = 0; kt < 32; kt++) {
        const int st = kt % 3;
        if (kt < 31) { CP_WAIT(1); } else { CP_WAIT(0); }
        __syncthreads();
        if (kt + 2 < 32) {
            load_kv((kt + 2) % 3, kt + 2); CP_COMMIT();
            if (tid < 64)
                msk[(kt + 2) % 3][tid] = mask[bbi * SS + (kt + 2) * 64 + tid] ? 0.f : -1e30f;
        }

        const uint32_t sKh = smb + AKV0 + st * ASTG;
        const uint32_t sKl = sKh + 8192;
        const uint32_t sVh = sKh + 16384;
        const uint32_t sVl = sKh + 24576;

        float s[8][4];
#pragma unroll
        for (int j = 0; j < 8; j++)
#pragma unroll
            for (int q = 0; q < 4; q++) s[j][q] = 0.f;
#pragma unroll
        for (int ks = 0; ks < 4; ks++) {
            const int colb = ks * 32 + csel;
            uint32_t kb[8][2], kl[8][2];
#pragma unroll
            for (int g = 0; g < 4; g++) {
                uint32_t off = SWZ((g * 16 + aro) * 128 + colb);
                uint32_t r0, r1, r2, r3;
                LDSM4(r0, r1, r2, r3, sKh + off);
                kb[2*g][0] = r0; kb[2*g][1] = r2; kb[2*g+1][0] = r1; kb[2*g+1][1] = r3;
                LDSM4(r0, r1, r2, r3, sKl + off);
                kl[2*g][0] = r0; kl[2*g][1] = r2; kl[2*g+1][0] = r1; kl[2*g+1][1] = r3;
            }
#pragma unroll
            for (int j = 0; j < 8; j++) {
                mma16816(s[j], qh[ks], kb[j]);
                mma16816(s[j], qh[ks], kl[j]);
                mma16816(s[j], ql[ks], kb[j]);
            }
        }

        const int c0 = (lane & 3) * 2;
        float mn0 = mi0, mn1 = mi1;
#pragma unroll
        for (int j = 0; j < 8; j++) {
            float mk0 = msk[st][j * 8 + c0], mk1 = msk[st][j * 8 + c0 + 1];
            s[j][0] += mk0; s[j][1] += mk1; s[j][2] += mk0; s[j][3] += mk1;
            mn0 = fmaxf(mn0, fmaxf(s[j][0], s[j][1]));
            mn1 = fmaxf(mn1, fmaxf(s[j][2], s[j][3]));
        }
        mn0 = fmaxf(mn0, __shfl_xor_sync(0xffffffffu, mn0, 1));
        mn0 = fmaxf(mn0, __shfl_xor_sync(0xffffffffu, mn0, 2));
        mn1 = fmaxf(mn1, __shfl_xor_sync(0xffffffffu, mn1, 1));
        mn1 = fmaxf(mn1, __shfl_xor_sync(0xffffffffu, mn1, 2));

        float a0 = __expf(mi0 - mn0), a1 = __expf(mi1 - mn1);
        float rs0 = 0.f, rs1 = 0.f;
        uint32_t pah[4][4], pal[4][4];
#pragma unroll
        for (int j = 0; j < 8; j++) {
            float p0 = __expf(s[j][0] - mn0), p1 = __expf(s[j][1] - mn0);
            float p2 = __expf(s[j][2] - mn1), p3 = __expf(s[j][3] - mn1);
            rs0 += p0 + p1; rs1 += p2 + p3;
            uint32_t h01, l01, h23, l23;
            splitpack2(p0, p1, h01, l01);
            splitpack2(p2, p3, h23, l23);
            pah[j >> 1][2*(j & 1) + 0] = h01; pah[j >> 1][2*(j & 1) + 1] = h23;
            pal[j >> 1][2*(j & 1) + 0] = l01; pal[j >> 1][2*(j & 1) + 1] = l23;
        }
        rs0 += __shfl_xor_sync(0xffffffffu, rs0, 1);
        rs0 += __shfl_xor_sync(0xffffffffu, rs0, 2);
        rs1 += __shfl_xor_sync(0xffffffffu, rs1, 1);
        rs1 += __shfl_xor_sync(0xffffffffu, rs1, 2);
        li0 = li0 * a0 + rs0; li1 = li1 * a1 + rs1;
        mi0 = mn0; mi1 = mn1;
#pragma unroll
        for (int j = 0; j < 8; j++) {
            o[j][0] *= a0; o[j][1] *= a0; o[j][2] *= a1; o[j][3] *= a1;
        }

#pragma unroll
        for (int ks = 0; ks < 4; ks++) {
            uint32_t vb[8][2], vl[8][2];
#pragma unroll
            for (int dt = 0; dt < 4; dt++) {
                uint32_t off = SWZ((ks * 16 + (lane & 15)) * 128 + dt * 32 + csel);
                uint32_t r0, r1, r2, r3;
                LDSM4T(r0, r1, r2, r3, sVh + off);
                vb[2*dt][0] = r0; vb[2*dt][1] = r1; vb[2*dt+1][0] = r2; vb[2*dt+1][1] = r3;
                LDSM4T(r0, r1, r2, r3, sVl + off);
                vl[2*dt][0] = r0; vl[2*dt][1] = r1; vl[2*dt+1][0] = r2; vl[2*dt+1][1] = r3;
            }
#pragma unroll
            for (int j = 0; j < 8; j++) {
                mma16816(o[j], pah[ks], vb[j]);
                mma16816(o[j], pah[ks], vl[j]);
                mma16816(o[j], pal[ks], vb[j]);
            }
        }
    }

    float inv0 = 1.f / li0, inv1 = 1.f / li1;
    int r0 = q0 + w * 16 + (lane >> 2);
#pragma unroll
    for (int j = 0; j < 8; j++) {
        int d = j * 8 + (lane & 3) * 2;
        float v0 = o[j][0] * inv0, v1 = o[j][1] * inv0;
        float v2 = o[j][2] * inv1, v3 = o[j][3] * inv1;
        uint32_t h01, l01, h23, l23;
        splitpack2(v0, v1, h01, l01);
        splitpack2(v2, v3, h23, l23);
        size_t i0 = (((size_t)bbi * SS + r0) * HH + hh) * DD + d;
        size_t i1 = (((size_t)bbi * SS + r0 + 8) * HH + hh) * DD + d;
        *(uint32_t*)&g_atthi[i0] = h01; *(uint32_t*)&g_attlo[i0] = l01;
        *(uint32_t*)&g_atthi[i1] = h23; *(uint32_t*)&g_attlo[i1] = l23;
    }
}

// ---------------------------------------------------------------------------
extern "C" void kernel_launch(void* const* d_in, const int* in_sizes, int n_in,
                              void* d_out, int out_size)
{
    const float* x     = (const float*)d_in[0];
    const int*   mask  = (const int*)  d_in[1];
    const float* qkv_w = (const float*)d_in[2];
    const float* out_w = (const float*)d_in[3];
    const float* out_b = (const float*)d_in[4];
    float*       out   = (float*)d_out;

    __nv_bfloat16 *xhi, *xlo, *wqhi, *wqlo, *wohi, *wolo, *athi, *atlo;
    cudaGetSymbolAddress((void**)&xhi,  g_xhi);  cudaGetSymbolAddress((void**)&xlo,  g_xlo);
    cudaGetSymbolAddress((void**)&wqhi, g_wqhi); cudaGetSymbolAddress((void**)&wqlo, g_wqlo);
    cudaGetSymbolAddress((void**)&wohi, g_wohi); cudaGetSymbolAddress((void**)&wolo, g_wolo);
    cudaGetSymbolAddress((void**)&athi, g_atthi); cudaGetSymbolAddress((void**)&atlo, g_attlo);

    cudaFuncSetAttribute(mm_mma,   cudaFuncAttributeMaxDynamicSharedMemorySize, GSMEM);
    cudaFuncSetAttribute(attn_mma, cudaFuncAttributeMaxDynamicSharedMemorySize, ASMEM);

    // 1) splits
    {
        int n4 = M1 * KDIM / 4;
        split_bf16<<<(n4 + 255) / 256, 256>>>(x, xhi, xlo, n4);
        n4 = N1 * KDIM / 4;
        split_bf16<<<(n4 + 255) / 256, 256>>>(qkv_w, wqhi, wqlo, n4);
        n4 = EE * KDIM / 4;
        split_bf16<<<(n4 + 255) / 256, 256>>>(out_w, wohi, wolo, n4);
    }

    // 2) QKV projection (HMMA, 512 threads), scatters bf16 hi/lo q/k/v
    {
        dim3 grid(N1 / 128, M1 / 128);   // 24 x 32
        mm_mma<<<grid, 512, GSMEM>>>(xhi, xlo, wqhi, wqlo, nullptr, nullptr, 0);
    }

    // 3) attention (HMMA FA2)
    {
        dim3 grid(SS / 128, BB * HH);    // 16 x 32
        attn_mma<<<grid, 256, ASMEM>>>(mask);
    }

    // 4) output projection (HMMA, 512 threads) + bias
    {
        dim3 grid(EE / 128, M1 / 128);   // 8 x 32
        mm_mma<<<grid, 512, GSMEM>>>(athi, atlo, wohi, wolo, out, out_b, 1);
    }
}